// round 16
// baseline (speedup 1.0000x reference)
#include <cuda_runtime.h>
#include <stdint.h>
#include <math_constants.h>

#define HH 2048
#define WW 2048
#define NPIX (HH * WW)

#define TW 32                    // tile width
#define TH 16                    // tile height
#define SW (TW + 2)              // 34 (halo 1)
#define SH (TH + 2)              // 18
#define NSLOT (SW * SH)          // 612

#define SW2 (TW + 4)             // 36 (halo 2, fused kernel)
#define SH2 (TH + 4)             // 20
#define NSLOT2 (SW2 * SH2)       // 720
#define SWA (TW + 2)             // 34 (core+1 region)
#define SHA (TH + 2)             // 18
#define NSLOTA (SWA * SHA)       // 612

#define NBX 64                   // tiles per row (bits in a mask word)
#define NBY 128                  // tile rows
#define NB  (NBX * NBY)          // 8192

#define GROWTH_ITERS 26          // single-step growth kernel
#define FUSED_LAUNCHES 36        // 72 iters fused (26..97)
// tail: iters 98,99 single-step quiet

typedef unsigned long long ull;

__device__ float g_scratch[NPIX];
__device__ ull g_chmask[3][NBY];   // changed bits, 3-parity rotation (per launch)
__device__ ull g_posmask[NBY];     // possible bits

// ---------------------------------------------------------------------------
// Threefry-2x32, 20 rounds — exact transcription of jax._src.prng
// ---------------------------------------------------------------------------
__host__ __device__ __forceinline__ uint32_t rotl32(uint32_t v, uint32_t r) {
#ifdef __CUDA_ARCH__
    return __funnelshift_l(v, v, r);
#else
    return (v << r) | (v >> (32u - r));
#endif
}

__host__ __device__ __forceinline__ void tf2x32(uint32_t k0, uint32_t k1,
                                                uint32_t x0, uint32_t x1,
                                                uint32_t& o0, uint32_t& o1) {
    uint32_t ks2 = k0 ^ k1 ^ 0x1BD11BDAu;
    x0 += k0; x1 += k1;
#define TF_R(r) { x0 += x1; x1 = rotl32(x1, r); x1 ^= x0; }
    TF_R(13u) TF_R(15u) TF_R(26u) TF_R(6u)
    x0 += k1;  x1 += ks2 + 1u;
    TF_R(17u) TF_R(29u) TF_R(16u) TF_R(24u)
    x0 += ks2; x1 += k0 + 2u;
    TF_R(13u) TF_R(15u) TF_R(26u) TF_R(6u)
    x0 += k0;  x1 += k1 + 3u;
    TF_R(17u) TF_R(29u) TF_R(16u) TF_R(24u)
    x0 += k1;  x1 += ks2 + 4u;
    TF_R(13u) TF_R(15u) TF_R(26u) TF_R(6u)
    x0 += ks2; x1 += k0 + 5u;
#undef TF_R
    o0 = x0; o1 = x1;
}

// Partitionable-mode random bits for flat index p: counter=(0,p); bits=o0^o1
__device__ __forceinline__ uint32_t pbits(uint32_t k0, uint32_t k1, uint32_t p) {
    uint32_t o0, o1;
    tf2x32(k0, k1, 0u, p, o0, o1);
    return o0 ^ o1;
}

__device__ __forceinline__ float bits_to_uniform(uint32_t bits) {
    return __fsub_rn(__uint_as_float((bits >> 9) | 0x3f800000u), 1.0f);
}

#define MAX9(A, a, b, m) do {                                   \
    m = A[a][b];                                                \
    m = fmaxf(m, A[a][b + 1]);   m = fmaxf(m, A[a][b + 2]);     \
    m = fmaxf(m, A[a + 1][b]);   m = fmaxf(m, A[a + 1][b + 1]); \
    m = fmaxf(m, A[a + 1][b + 2]);                              \
    m = fmaxf(m, A[a + 2][b]);   m = fmaxf(m, A[a + 2][b + 1]); \
    m = fmaxf(m, A[a + 2][b + 2]); } while (0)

// ---------------------------------------------------------------------------
// x0 = seed * habitat * goodness  (+ reset masks)
// ---------------------------------------------------------------------------
__global__ void init_kernel(const float* __restrict__ seed,
                            const float* __restrict__ hab,
                            const float* __restrict__ good,
                            float* __restrict__ xout) {
    int idx = blockIdx.x * blockDim.x + threadIdx.x;
    if (idx < NPIX / 4) {
        const float4 s = ((const float4*)seed)[idx];
        const float4 h = ((const float4*)hab)[idx];
        const float4 g = ((const float4*)good)[idx];
        float4 o;
        o.x = __fmul_rn(__fmul_rn(s.x, h.x), g.x);
        o.y = __fmul_rn(__fmul_rn(s.y, h.y), g.y);
        o.z = __fmul_rn(__fmul_rn(s.z, h.z), g.z);
        o.w = __fmul_rn(__fmul_rn(s.w, h.w), g.w);
        ((float4*)xout)[idx] = o;
    }
    if (idx < NBY) {
        g_chmask[2][idx] = ~0ull;   // prev parity of launch 0 -> force all
        g_chmask[0][idx] = 0ull;
        g_chmask[1][idx] = 0ull;
        g_posmask[idx]   = 0ull;
    }
}

// ---------------------------------------------------------------------------
// GROWTH kernel: one tile per block, cipher work COMPACTED into dense lists.
// Dominance prune (validated exact in R15): noise cipher needed only for
// cells with x >= RN(0.9999*M[w]) for some adjacent pos window w; skipped
// cells contribute y1=0 which cannot be the window argmax. Candidates are
// provably in-image (x >= tm > 0.049), so no clamps in the cipher loops.
// ---------------------------------------------------------------------------
__global__ __launch_bounds__(256)
void growth_kernel(const float* __restrict__ xin, float* __restrict__ xout,
                   const float* __restrict__ good,
                   uint32_t k1a, uint32_t k1b, uint32_t k2a, uint32_t k2b,
                   int prev, int cur, int nxt) {
    __shared__ float xs[SH][SW];
    __shared__ float ys[SH][SW];
    __shared__ float Ts[SH][SW];             // thresholds, then y5 (core)
    __shared__ unsigned short s_poslist[512];
    __shared__ unsigned short s_noiselist[NSLOT];
    __shared__ int s_np, s_nn;

    const int tid = threadIdx.x;
    const int tx = tid & 31;
    const int ty = tid >> 5;

    if (blockIdx.x < NBY && tid == 0) g_chmask[nxt][blockIdx.x] = 0ull;

    const int by = blockIdx.x >> 6;
    const int bx = blockIdx.x & 63;

    ull nbm = g_chmask[prev][by];
    const ull chm = nbm;
    if (by > 0)       nbm |= g_chmask[prev][by - 1];
    if (by < NBY - 1) nbm |= g_chmask[prev][by + 1];
    const ull posw = g_posmask[by];

    const ull colm = (bx == 0) ? 3ull : (7ull << (bx - 1));
    const bool need = ((nbm & colm) != 0ull) || (((posw >> bx) & 1ull) != 0ull);
    if (!need) return;

    const int selfchg = (int)((chm >> bx) & 1ull);
    const int c0 = bx * TW, r0 = by * TH;

    float gd[2];
    #pragma unroll
    for (int k = 0; k < 2; k++)
        gd[k] = good[(r0 + ty + k * 8) * WW + c0 + tx];

    // ==== load xs (coalesced core + halo ring); zero ys; zero counters ====
    if (tid < 128) {
        int row = tid >> 3, q = tid & 7;
        const float4 v = *(const float4*)&xin[(r0 + row) * WW + c0 + q * 4];
        float* dst = &xs[row + 1][1 + q * 4];
        dst[0] = v.x; dst[1] = v.y; dst[2] = v.z; dst[3] = v.w;
    } else {
        int h = tid - 128;
        if (h < 100) {
            int j, i;
            if (h < 34)      { j = 0;             i = h; }
            else if (h < 68) { j = SH - 1;        i = h - 34; }
            else if (h < 84) { j = 1 + (h - 68);  i = 0; }
            else             { j = 1 + (h - 84);  i = SW - 1; }
            int r = r0 - 1 + j, c = c0 - 1 + i;
            bool ok = (r >= 0) && (r < HH) && (c >= 0) && (c < WW);
            xs[j][i] = ok ? xin[r * WW + c] : 0.0f;
        }
    }
    #pragma unroll
    for (int k = 0; k < 3; k++) {
        int s = tid + k * 256;
        if (s < NSLOT) ys[s / SW][s % SW] = 0.0f;
    }
    if (tid == 0) { s_np = 0; s_nn = 0; }
    __syncthreads();

    // ==== phase A: pos test, thresholds, pos-list append ====
    float xx[2], M[2];
    bool  pos[2];
    #pragma unroll
    for (int k = 0; k < 2; k++) {
        int jj = 1 + ty + k * 8, ii = 1 + tx;
        float m;
        MAX9(xs, jj - 1, ii - 1, m);
        M[k]  = m;
        xx[k] = xs[jj][ii];
        pos[k] = __fsub_rn(__fmul_rn(m, gd[k]), xx[k]) > 0.05f;
        Ts[jj][ii] = pos[k] ? __fmul_rn(0.9999f, m) : CUDART_INF_F;
        unsigned b = __ballot_sync(0xffffffffu, pos[k]);
        int base = 0;
        if (tx == 0 && b) base = atomicAdd(&s_np, __popc(b));
        base = __shfl_sync(0xffffffffu, base, 0);
        if (pos[k]) {
            int rank = __popc(b & ((1u << tx) - 1u));
            s_poslist[base + rank] = (unsigned short)(jj * SW + ii);
        }
    }
    __syncthreads();
    const int np = s_np;

    if (np == 0) {
        if (selfchg) {
            #pragma unroll
            for (int k = 0; k < 2; k++)
                xout[(r0 + ty + k * 8) * WW + c0 + tx] = xx[k];
        }
        if (tid == 0 && ((posw >> bx) & 1ull))
            atomicAnd(&g_posmask[by], ~(1ull << bx));
        return;
    }

    // ==== phase B: dominance scan -> noise candidate list ====
    #pragma unroll
    for (int k = 0; k < 3; k++) {
        int s = tid + k * 256;
        bool sv = s < NSLOT;
        int ss = sv ? s : 0;
        int j = ss / SW, ii = ss % SW;
        float x = sv ? xs[j][ii] : 0.0f;
        float tm = CUDART_INF_F;
        #pragma unroll
        for (int dj = -1; dj <= 1; dj++) {
            int a = j + dj;
            if (a < 1 || a > TH) continue;
            #pragma unroll
            for (int di = -1; di <= 1; di++) {
                int b2 = ii + di;
                if (b2 < 1 || b2 > TW) continue;
                tm = fminf(tm, Ts[a][b2]);
            }
        }
        bool needc = sv && (x >= tm);            // tm > 0.049 -> in-image
        unsigned b = __ballot_sync(0xffffffffu, needc);
        int base = 0;
        if (tx == 0 && b) base = atomicAdd(&s_nn, __popc(b));
        base = __shfl_sync(0xffffffffu, base, 0);
        if (needc) {
            int rank = __popc(b & ((1u << tx) - 1u));
            s_noiselist[base + rank] = (unsigned short)(j * SW + ii);
        }
    }
    __syncthreads();
    const int nn = s_nn;

    // ==== phase C: dense noise ciphers (every lane useful) ====
    for (int i = tid; i < nn; i += 256) {
        int slot = s_noiselist[i];
        int j = slot / SW, ii = slot % SW;
        uint32_t p = (uint32_t)((r0 - 1 + j) * WW + (c0 - 1 + ii));
        float u = bits_to_uniform(pbits(k1a, k1b, p));
        float f = __fadd_rn(0.9999f, __fmul_rn(1e-4f, u));
        ys[j][ii] = __fmul_rn(xs[j][ii], f);
    }
    __syncthreads();

    // ==== phase D: dense coin ciphers over pos cells; y5 -> Ts ====
    for (int i = tid; i < np; i += 256) {
        int slot = s_poslist[i];
        int jj = slot / SW, ii = slot % SW;
        float m;
        MAX9(ys, jj - 1, ii - 1, m);
        uint32_t p = (uint32_t)((r0 - 1 + jj) * WW + (c0 - 1 + ii));
        uint32_t bits = pbits(k2a, k2b, p);
        bool coin = ((bits >> 9) > 0x400000u);
        float y4 = 0.0f;
        if (coin && m > 0.0f) y4 = __fmul_rn(m, good[p]);
        float d  = __fsub_rn(y4, xs[jj][ii]);
        Ts[jj][ii] = (d > 0.05f) ? y4 : 0.0f;    // y5
    }
    __syncthreads();

    // ==== phase E: write out ====
    int chg = 0;
    #pragma unroll
    for (int k = 0; k < 2; k++) {
        int jj = 1 + ty + k * 8, ii = 1 + tx;
        float out = pos[k] ? fmaxf(Ts[jj][ii], xx[k]) : xx[k];
        xout[(r0 + ty + k * 8) * WW + c0 + tx] = out;
        chg |= (out != xx[k]) ? 1 : 0;
    }
    int anychg = __syncthreads_or(chg);
    if (tid == 0) {
        ull bit = 1ull << bx;
        if (anychg) atomicOr(&g_chmask[cur][by], bit);
        if (!((posw >> bx) & 1ull)) atomicOr(&g_posmask[by], bit);
    }
}

// ---------------------------------------------------------------------------
// Quiet single step (R14-exact): 4 tiles/block, pretest, bitmask gating.
// ---------------------------------------------------------------------------
__global__ __launch_bounds__(256)
void quiet_kernel(const float* __restrict__ xin, float* __restrict__ xout,
                  const float* __restrict__ good,
                  uint32_t k1a, uint32_t k1b, uint32_t k2a, uint32_t k2b,
                  int prev, int cur, int nxt) {
    __shared__ float xs[SH][SW];
    __shared__ float ys[SH][SW];
    __shared__ unsigned s_rowpos[TH];

    const int tid = threadIdx.x;
    const int tx = tid & 31;
    const int ty = tid >> 5;

    if (blockIdx.x < NBY && tid == 0) g_chmask[nxt][blockIdx.x] = 0ull;

    const int tbase = blockIdx.x * 4;
    const int by  = tbase >> 6;
    const int bx0 = tbase & 63;

    ull nbm = g_chmask[prev][by];
    const ull chm = nbm;
    if (by > 0)       nbm |= g_chmask[prev][by - 1];
    if (by < NBY - 1) nbm |= g_chmask[prev][by + 1];
    const ull posw = g_posmask[by];

    #pragma unroll
    for (int kt = 0; kt < 4; kt++) {
        const int bx = bx0 + kt;
        const ull colm = (bx == 0) ? 3ull : (7ull << (bx - 1));
        const bool need = ((nbm & colm) != 0ull) || (((posw >> bx) & 1ull) != 0ull);
        if (!need) continue;

        const int selfchg = (int)((chm >> bx) & 1ull);
        const int c0 = bx * TW, r0 = by * TH;

        __syncthreads();

        if (tid < 128) {
            int row = tid >> 3, q = tid & 7;
            const float4 v = *(const float4*)&xin[(r0 + row) * WW + c0 + q * 4];
            float* dst = &xs[row + 1][1 + q * 4];
            dst[0] = v.x; dst[1] = v.y; dst[2] = v.z; dst[3] = v.w;
        } else {
            int h = tid - 128;
            if (h < 100) {
                int j, i;
                if (h < 34)      { j = 0;             i = h; }
                else if (h < 68) { j = SH - 1;        i = h - 34; }
                else if (h < 84) { j = 1 + (h - 68);  i = 0; }
                else             { j = 1 + (h - 84);  i = SW - 1; }
                int r = r0 - 1 + j, c = c0 - 1 + i;
                bool ok = (r >= 0) && (r < HH) && (c >= 0) && (c < WW);
                xs[j][i] = ok ? xin[r * WW + c] : 0.0f;
            }
        }
        __syncthreads();

        float xx[2], M[2];
        bool  pre[2];
        #pragma unroll
        for (int k = 0; k < 2; k++) {
            int jj = 1 + ty + k * 8, ii = 1 + tx;
            float m;
            MAX9(xs, jj - 1, ii - 1, m);
            M[k]  = m;
            xx[k] = xs[jj][ii];
            pre[k] = __fsub_rn(m, xx[k]) > 0.05f;
        }
        int anyPre = __syncthreads_or((pre[0] || pre[1]) ? 1 : 0);

        float gd[2];
        bool  pos[2] = {false, false};
        int   any = 0;
        if (anyPre) {
            #pragma unroll
            for (int k = 0; k < 2; k++) {
                gd[k] = good[(r0 + ty + k * 8) * WW + c0 + tx];
                pos[k] = pre[k] &&
                         (__fsub_rn(__fmul_rn(M[k], gd[k]), xx[k]) > 0.05f);
                unsigned rowmask = __ballot_sync(0xffffffffu, pos[k]);
                if (tx == 0) s_rowpos[ty + k * 8] = rowmask;
            }
            any = __syncthreads_or((pos[0] || pos[1]) ? 1 : 0);
        }

        if (!any) {
            if (selfchg) {
                #pragma unroll
                for (int k = 0; k < 2; k++)
                    xout[(r0 + ty + k * 8) * WW + c0 + tx] = xx[k];
            }
            if (tid == 0 && ((posw >> bx) & 1ull))
                atomicAnd(&g_posmask[by], ~(1ull << bx));
            continue;
        }

        #pragma unroll
        for (int k = 0; k < 3; k++) {
            int s = tid + k * 256;
            bool sv = s < NSLOT;
            int ss = sv ? s : 0;
            int j = ss / SW, ii = ss % SW;
            float x = sv ? xs[j][ii] : 0.0f;
            unsigned rm = 0;
            #pragma unroll
            for (int dr = 0; dr < 3; dr++) {
                int cr = j - 2 + dr;
                if (cr >= 0 && cr < TH) rm |= s_rowpos[cr];
            }
            ull rm2 = ((ull)rm) << 2;
            bool needc = (((rm2 >> ii) & 7ull) != 0ull) && (x > 0.05f);
            float y1 = 0.0f;
            if (__ballot_sync(0xffffffffu, needc)) {
                int r = r0 - 1 + j, c = c0 - 1 + ii;
                uint32_t p = (uint32_t)(min(max(r, 0), HH - 1) * WW +
                                        min(max(c, 0), WW - 1));
                float u = bits_to_uniform(pbits(k1a, k1b, p));
                float f = __fadd_rn(0.9999f, __fmul_rn(1e-4f, u));
                y1 = __fmul_rn(x, f);
            }
            if (sv) ys[j][ii] = y1;
        }
        __syncthreads();

        int chg = 0;
        #pragma unroll
        for (int k = 0; k < 2; k++) {
            int jj = 1 + ty + k * 8, ii = 1 + tx;
            float m;
            MAX9(ys, jj - 1, ii - 1, m);
            uint32_t p = (uint32_t)((r0 + ty + k * 8) * WW + c0 + tx);
            float y4 = 0.0f;
            if (__ballot_sync(0xffffffffu, pos[k])) {
                uint32_t bits = pbits(k2a, k2b, p);
                bool coin = ((bits >> 9) > 0x400000u);
                if (coin && m > 0.0f) y4 = __fmul_rn(m, gd[k]);
            }
            float d  = __fsub_rn(y4, xx[k]);
            float y5 = (d > 0.05f) ? y4 : 0.0f;
            float out = fmaxf(y5, xx[k]);
            xout[p] = out;
            chg |= (out != xx[k]) ? 1 : 0;
        }
        int anychg = __syncthreads_or(chg);
        if (tid == 0) {
            ull bit = 1ull << bx;
            if (anychg) atomicOr(&g_chmask[cur][by], bit);
            if (!((posw >> bx) & 1ull)) atomicOr(&g_posmask[by], bit);
        }
    }
}

// ---------------------------------------------------------------------------
// TWO fused iterations per launch (quiet phase) — R14-exact, unchanged.
// ---------------------------------------------------------------------------
__global__ __launch_bounds__(256)
void fused_kernel(const float* __restrict__ xin, float* __restrict__ xout,
                  const float* __restrict__ good,
                  uint32_t kA1a, uint32_t kA1b, uint32_t kA2a, uint32_t kA2b,
                  uint32_t kB1a, uint32_t kB1b, uint32_t kB2a, uint32_t kB2b,
                  int prev, int cur, int nxt) {
    __shared__ float xs[SH2][SW2];
    __shared__ float ys[SH2][SW2];
    __shared__ float xa[SHA][SWA];
    __shared__ float gs[SHA][SWA];
    __shared__ ull s_posA[SHA];
    __shared__ unsigned s_rowposB[TH];

    const int tid = threadIdx.x;
    const int tx = tid & 31;
    const int ty = tid >> 5;

    if (blockIdx.x < NBY && tid == 0) g_chmask[nxt][blockIdx.x] = 0ull;

    const int tbase = blockIdx.x * 2;
    const int by  = tbase >> 6;
    const int bx0 = tbase & 63;

    ull needw = 0ull;
    const ull chm = g_chmask[prev][by];
    {
        ull a = chm | g_posmask[by];
        needw |= a | (a << 1) | (a >> 1);
        if (by > 0) {
            ull b = g_chmask[prev][by - 1] | g_posmask[by - 1];
            needw |= b | (b << 1) | (b >> 1);
        }
        if (by < NBY - 1) {
            ull c = g_chmask[prev][by + 1] | g_posmask[by + 1];
            needw |= c | (c << 1) | (c >> 1);
        }
    }
    const ull posw = g_posmask[by];

    #pragma unroll
    for (int kt = 0; kt < 2; kt++) {
        const int bx = bx0 + kt;
        if (!((needw >> bx) & 1ull)) continue;

        const int selfchg = (int)((chm >> bx) & 1ull);
        const int c0 = bx * TW, r0 = by * TH;

        __syncthreads();

        #pragma unroll
        for (int q = 0; q < 3; q++) {
            int s = tid + q * 256;
            if (s < NSLOT2) {
                int j = s / SW2, i = s % SW2;
                int r = r0 - 2 + j, c = c0 - 2 + i;
                bool ok = (r >= 0) && (r < HH) && (c >= 0) && (c < WW);
                xs[j][i] = ok ? xin[r * WW + c] : 0.0f;
            }
        }
        if (tid < SHA) s_posA[tid] = 0ull;
        __syncthreads();

        bool posAv[3]; float xxA[3], gsv[3];
        #pragma unroll
        for (int q = 0; q < 3; q++) {
            int s = tid + q * 256;
            bool sv = s < NSLOTA;
            posAv[q] = false; xxA[q] = 0.0f; gsv[q] = 0.0f;
            if (sv) {
                int a = s / SWA, b = s % SWA;
                int r = r0 - 1 + a, c = c0 - 1 + b;
                bool inim = (r >= 0) && (r < HH) && (c >= 0) && (c < WW);
                float g = inim ? good[r * WW + c] : 0.0f;
                gsv[q] = g; gs[a][b] = g;
                float x = xs[a + 1][b + 1];
                xxA[q] = x;
                float M; MAX9(xs, a, b, M);
                if (inim && (__fsub_rn(__fmul_rn(M, g), x) > 0.05f)) {
                    posAv[q] = true;
                    atomicOr(&s_posA[a], 1ull << b);
                }
            }
        }
        int anyA = __syncthreads_or((posAv[0] || posAv[1] || posAv[2]) ? 1 : 0);

        if (!anyA) {
            if (selfchg) {
                #pragma unroll
                for (int k = 0; k < 2; k++) {
                    int rr = ty + k * 8, cc = tx;
                    xout[(r0 + rr) * WW + (c0 + cc)] = xs[rr + 2][cc + 2];
                }
            }
            if (tid == 0 && ((posw >> bx) & 1ull))
                atomicAnd(&g_posmask[by], ~(1ull << bx));
            continue;
        }

        #pragma unroll
        for (int q = 0; q < 3; q++) {
            int s = tid + q * 256;
            bool sv = s < NSLOT2;
            int j = sv ? s / SW2 : 0, i = sv ? s % SW2 : 0;
            float x = sv ? xs[j][i] : 0.0f;
            ull rm = 0ull;
            #pragma unroll
            for (int dr = 0; dr < 3; dr++) {
                int ar = j - 2 + dr;
                if (ar >= 0 && ar < SHA) rm |= s_posA[ar];
            }
            ull rm2 = rm << 2;
            bool needc = (((rm2 >> i) & 7ull) != 0ull) && (x > 0.05f);
            float y1 = 0.0f;
            if (__ballot_sync(0xffffffffu, needc)) {
                int r = r0 - 2 + j, c = c0 - 2 + i;
                uint32_t p = (uint32_t)(min(max(r, 0), HH - 1) * WW +
                                        min(max(c, 0), WW - 1));
                float u = bits_to_uniform(pbits(kA1a, kA1b, p));
                float f = __fadd_rn(0.9999f, __fmul_rn(1e-4f, u));
                y1 = __fmul_rn(x, f);
            }
            if (sv) ys[j][i] = y1;
        }
        __syncthreads();

        #pragma unroll
        for (int q = 0; q < 3; q++) {
            int s = tid + q * 256;
            bool sv = s < NSLOTA;
            int a = sv ? s / SWA : 0, b = sv ? s % SWA : 0;
            float m; MAX9(ys, a, b, m);
            float y4 = 0.0f;
            if (__ballot_sync(0xffffffffu, posAv[q])) {
                int r = r0 - 1 + a, c = c0 - 1 + b;
                uint32_t p = (uint32_t)(min(max(r, 0), HH - 1) * WW +
                                        min(max(c, 0), WW - 1));
                uint32_t bits = pbits(kA2a, kA2b, p);
                bool coin = ((bits >> 9) > 0x400000u);
                if (coin && m > 0.0f) y4 = __fmul_rn(m, gsv[q]);
            }
            float d  = __fsub_rn(y4, xxA[q]);
            float y5 = (d > 0.05f) ? y4 : 0.0f;
            if (sv) xa[a][b] = fmaxf(y5, xxA[q]);
        }
        __syncthreads();

        bool posB[2]; float xab[2], gdB[2];
        #pragma unroll
        for (int k = 0; k < 2; k++) {
            int rr = ty + k * 8, cc = tx;
            float M; MAX9(xa, rr, cc, M);
            xab[k] = xa[rr + 1][cc + 1];
            gdB[k] = gs[rr + 1][cc + 1];
            posB[k] = __fsub_rn(__fmul_rn(M, gdB[k]), xab[k]) > 0.05f;
            unsigned rowmask = __ballot_sync(0xffffffffu, posB[k]);
            if (tx == 0) s_rowposB[rr] = rowmask;
        }
        int anyB = __syncthreads_or((posB[0] || posB[1]) ? 1 : 0);

        if (!anyB) {
            int chg = 0;
            #pragma unroll
            for (int k = 0; k < 2; k++) {
                int rr = ty + k * 8, cc = tx;
                float out = xab[k];
                xout[(r0 + rr) * WW + (c0 + cc)] = out;
                chg |= (out != xs[rr + 2][cc + 2]) ? 1 : 0;
            }
            int anychg = __syncthreads_or(chg);
            if (tid == 0) {
                if (anychg) atomicOr(&g_chmask[cur][by], 1ull << bx);
                if ((posw >> bx) & 1ull)
                    atomicAnd(&g_posmask[by], ~(1ull << bx));
            }
            continue;
        }

        #pragma unroll
        for (int q = 0; q < 3; q++) {
            int s = tid + q * 256;
            bool sv = s < NSLOTA;
            int a = sv ? s / SWA : 0, b = sv ? s % SWA : 0;
            float x = sv ? xa[a][b] : 0.0f;
            unsigned rm = 0;
            #pragma unroll
            for (int dr = 0; dr < 3; dr++) {
                int br = a - 2 + dr;
                if (br >= 0 && br < TH) rm |= s_rowposB[br];
            }
            ull rm2 = ((ull)rm) << 2;
            bool needc = (((rm2 >> b) & 7ull) != 0ull) && (x > 0.05f);
            float y1 = 0.0f;
            if (__ballot_sync(0xffffffffu, needc)) {
                int r = r0 - 1 + a, c = c0 - 1 + b;
                uint32_t p = (uint32_t)(min(max(r, 0), HH - 1) * WW +
                                        min(max(c, 0), WW - 1));
                float u = bits_to_uniform(pbits(kB1a, kB1b, p));
                float f = __fadd_rn(0.9999f, __fmul_rn(1e-4f, u));
                y1 = __fmul_rn(x, f);
            }
            if (sv) ys[a][b] = y1;
        }
        __syncthreads();

        int chg = 0;
        #pragma unroll
        for (int k = 0; k < 2; k++) {
            int rr = ty + k * 8, cc = tx;
            float m; MAX9(ys, rr, cc, m);
            uint32_t p = (uint32_t)((r0 + rr) * WW + (c0 + cc));
            float y4 = 0.0f;
            if (__ballot_sync(0xffffffffu, posB[k])) {
                uint32_t bits = pbits(kB2a, kB2b, p);
                bool coin = ((bits >> 9) > 0x400000u);
                if (coin && m > 0.0f) y4 = __fmul_rn(m, gdB[k]);
            }
            float d  = __fsub_rn(y4, xab[k]);
            float y5 = (d > 0.05f) ? y4 : 0.0f;
            float out = fmaxf(y5, xab[k]);
            xout[p] = out;
            chg |= (out != xs[rr + 2][cc + 2]) ? 1 : 0;
        }
        int anychg = __syncthreads_or(chg);
        if (tid == 0) {
            ull bit = 1ull << bx;
            if (anychg) atomicOr(&g_chmask[cur][by], bit);
            if (!((posw >> bx) & 1ull)) atomicOr(&g_posmask[by], bit);
        }
    }
}

// ---------------------------------------------------------------------------
// Host schedule: 26 growth (compacted) + 36 fused + 2 quiet singles.
// ---------------------------------------------------------------------------
static void iter_keys(int i, uint32_t* k) {
    uint32_t f0, f1;
    tf2x32(0u, 42u, 0u, (uint32_t)i, f0, f1);        // fold_in
    tf2x32(f0, f1, 0u, 0u, k[0], k[1]);              // split k1
    tf2x32(f0, f1, 0u, 1u, k[2], k[3]);              // split k2
}

extern "C" void kernel_launch(void* const* d_in, const int* in_sizes, int n_in,
                              void* d_out, int out_size) {
    const float* seed = (const float*)d_in[0];
    const float* hab  = (const float*)d_in[1];
    const float* good = (const float*)d_in[2];
    float* xout = (float*)d_out;

    float* scratch = nullptr;
    cudaGetSymbolAddress((void**)&scratch, g_scratch);

    init_kernel<<<(NPIX / 4 + 255) / 256, 256>>>(seed, hab, good, xout);

    const float* cura = xout;
    float*       alt  = scratch;
    int l = 0;

    for (int i = 0; i < GROWTH_ITERS; i++, l++) {
        uint32_t k[4];
        iter_keys(i, k);
        growth_kernel<<<NB, 256>>>(cura, alt, good, k[0], k[1], k[2], k[3],
                                   (l + 2) % 3, l % 3, (l + 1) % 3);
        const float* t = cura; cura = alt; alt = (float*)t;
    }

    for (int t = 0; t < FUSED_LAUNCHES; t++, l++) {
        uint32_t kA[4], kB[4];
        iter_keys(GROWTH_ITERS + 2 * t, kA);
        iter_keys(GROWTH_ITERS + 2 * t + 1, kB);
        fused_kernel<<<NB / 2, 256>>>(cura, alt, good,
                                      kA[0], kA[1], kA[2], kA[3],
                                      kB[0], kB[1], kB[2], kB[3],
                                      (l + 2) % 3, l % 3, (l + 1) % 3);
        const float* tt = cura; cura = alt; alt = (float*)tt;
    }

    for (int i = 98; i < 100; i++, l++) {
        uint32_t k[4];
        iter_keys(i, k);
        quiet_kernel<<<NB / 4, 256>>>(cura, alt, good,
                                      k[0], k[1], k[2], k[3],
                                      (l + 2) % 3, l % 3, (l + 1) % 3);
        const float* t = cura; cura = alt; alt = (float*)t;
    }
    // swaps: 26 + 36 + 2 = 64 (even) -> final state is in xout == d_out
}

// round 17
// speedup vs baseline: 1.1772x; 1.1772x over previous
#include <cuda_runtime.h>
#include <stdint.h>

#define HH 2048
#define WW 2048
#define NPIX (HH * WW)

#define TW 32                    // tile width
#define TH 16                    // tile height
#define SW (TW + 2)              // 34 (halo 1)
#define SH (TH + 2)              // 18
#define NSLOT (SW * SH)          // 612

#define SW2 (TW + 4)             // 36 (halo 2, fused kernel)
#define SH2 (TH + 4)             // 20
#define NSLOT2 (SW2 * SH2)       // 720
#define SWA (TW + 2)             // 34 (core+1 region)
#define SHA (TH + 2)             // 18
#define NSLOTA (SWA * SHA)       // 612

#define NBX 64                   // tiles per row (bits in a mask word)
#define NBY 128                  // tile rows
#define NB  (NBX * NBY)          // 8192

#define GROWTH_ITERS 26          // single-step growth kernel (iters 0..25)
#define FUSED_LAUNCHES 37        // 74 iters fused (26..99)

typedef unsigned long long ull;

__device__ float g_scratch[NPIX];
__device__ ull g_chmask[3][NBY];   // changed bits, 3-parity rotation (per launch)
__device__ ull g_posmask[NBY];     // possible bits

// ---------------------------------------------------------------------------
// Threefry-2x32, 20 rounds — exact transcription of jax._src.prng
// ---------------------------------------------------------------------------
__host__ __device__ __forceinline__ uint32_t rotl32(uint32_t v, uint32_t r) {
#ifdef __CUDA_ARCH__
    return __funnelshift_l(v, v, r);
#else
    return (v << r) | (v >> (32u - r));
#endif
}

__host__ __device__ __forceinline__ void tf2x32(uint32_t k0, uint32_t k1,
                                                uint32_t x0, uint32_t x1,
                                                uint32_t& o0, uint32_t& o1) {
    uint32_t ks2 = k0 ^ k1 ^ 0x1BD11BDAu;
    x0 += k0; x1 += k1;
#define TF_R(r) { x0 += x1; x1 = rotl32(x1, r); x1 ^= x0; }
    TF_R(13u) TF_R(15u) TF_R(26u) TF_R(6u)
    x0 += k1;  x1 += ks2 + 1u;
    TF_R(17u) TF_R(29u) TF_R(16u) TF_R(24u)
    x0 += ks2; x1 += k0 + 2u;
    TF_R(13u) TF_R(15u) TF_R(26u) TF_R(6u)
    x0 += k0;  x1 += k1 + 3u;
    TF_R(17u) TF_R(29u) TF_R(16u) TF_R(24u)
    x0 += k1;  x1 += ks2 + 4u;
    TF_R(13u) TF_R(15u) TF_R(26u) TF_R(6u)
    x0 += ks2; x1 += k0 + 5u;
#undef TF_R
    o0 = x0; o1 = x1;
}

// Partitionable-mode random bits for flat index p: counter=(0,p); bits=o0^o1
__device__ __forceinline__ uint32_t pbits(uint32_t k0, uint32_t k1, uint32_t p) {
    uint32_t o0, o1;
    tf2x32(k0, k1, 0u, p, o0, o1);
    return o0 ^ o1;
}

__device__ __forceinline__ float bits_to_uniform(uint32_t bits) {
    return __fsub_rn(__uint_as_float((bits >> 9) | 0x3f800000u), 1.0f);
}

#define MAX9(A, a, b, m) do {                                   \
    m = A[a][b];                                                \
    m = fmaxf(m, A[a][b + 1]);   m = fmaxf(m, A[a][b + 2]);     \
    m = fmaxf(m, A[a + 1][b]);   m = fmaxf(m, A[a + 1][b + 1]); \
    m = fmaxf(m, A[a + 1][b + 2]);                              \
    m = fmaxf(m, A[a + 2][b]);   m = fmaxf(m, A[a + 2][b + 1]); \
    m = fmaxf(m, A[a + 2][b + 2]); } while (0)

// ---------------------------------------------------------------------------
// x0 = seed * habitat * goodness  (+ reset masks)
// ---------------------------------------------------------------------------
__global__ void init_kernel(const float* __restrict__ seed,
                            const float* __restrict__ hab,
                            const float* __restrict__ good,
                            float* __restrict__ xout) {
    int idx = blockIdx.x * blockDim.x + threadIdx.x;
    if (idx < NPIX / 4) {
        const float4 s = ((const float4*)seed)[idx];
        const float4 h = ((const float4*)hab)[idx];
        const float4 g = ((const float4*)good)[idx];
        float4 o;
        o.x = __fmul_rn(__fmul_rn(s.x, h.x), g.x);
        o.y = __fmul_rn(__fmul_rn(s.y, h.y), g.y);
        o.z = __fmul_rn(__fmul_rn(s.z, h.z), g.z);
        o.w = __fmul_rn(__fmul_rn(s.w, h.w), g.w);
        ((float4*)xout)[idx] = o;
    }
    if (idx < NBY) {
        g_chmask[2][idx] = ~0ull;   // prev parity of launch 0 -> force all
        g_chmask[0][idx] = 0ull;
        g_chmask[1][idx] = 0ull;
        g_posmask[idx]   = 0ull;
    }
}

// ---------------------------------------------------------------------------
// GROWTH kernel (R14-exact body): 1 tile/block, good-load overlapped with
// the x tile load, no pretest. Noise gate: pos-mask dilated 1px AND x>0.05
// (exact). RNG index p is arithmetic-only -> no clamps needed (out-of-image
// lanes have x=0 -> y1=0; in-image non-candidates compute their correct y1).
// ---------------------------------------------------------------------------
__global__ __launch_bounds__(256)
void growth_kernel(const float* __restrict__ xin, float* __restrict__ xout,
                   const float* __restrict__ good,
                   uint32_t k1a, uint32_t k1b, uint32_t k2a, uint32_t k2b,
                   int prev, int cur, int nxt) {
    __shared__ float xs[SH][SW];
    __shared__ float ys[SH][SW];
    __shared__ unsigned s_rowpos[TH];

    const int tid = threadIdx.x;
    const int tx = tid & 31;
    const int ty = tid >> 5;

    if (blockIdx.x < NBY && tid == 0) g_chmask[nxt][blockIdx.x] = 0ull;

    const int by = blockIdx.x >> 6;
    const int bx = blockIdx.x & 63;

    ull nbm = g_chmask[prev][by];
    const ull chm = nbm;
    if (by > 0)       nbm |= g_chmask[prev][by - 1];
    if (by < NBY - 1) nbm |= g_chmask[prev][by + 1];
    const ull posw = g_posmask[by];

    const ull colm = (bx == 0) ? 3ull : (7ull << (bx - 1));
    const bool need = ((nbm & colm) != 0ull) || (((posw >> bx) & 1ull) != 0ull);
    if (!need) return;

    const int selfchg = (int)((chm >> bx) & 1ull);
    const int c0 = bx * TW, r0 = by * TH;

    float gd[2];
    #pragma unroll
    for (int k = 0; k < 2; k++)
        gd[k] = good[(r0 + ty + k * 8) * WW + c0 + tx];

    if (tid < 128) {
        int row = tid >> 3, q = tid & 7;
        const float4 v = *(const float4*)&xin[(r0 + row) * WW + c0 + q * 4];
        float* dst = &xs[row + 1][1 + q * 4];
        dst[0] = v.x; dst[1] = v.y; dst[2] = v.z; dst[3] = v.w;
    } else {
        int h = tid - 128;
        if (h < 100) {
            int j, i;
            if (h < 34)      { j = 0;             i = h; }
            else if (h < 68) { j = SH - 1;        i = h - 34; }
            else if (h < 84) { j = 1 + (h - 68);  i = 0; }
            else             { j = 1 + (h - 84);  i = SW - 1; }
            int r = r0 - 1 + j, c = c0 - 1 + i;
            bool ok = (r >= 0) && (r < HH) && (c >= 0) && (c < WW);
            xs[j][i] = ok ? xin[r * WW + c] : 0.0f;
        }
    }
    __syncthreads();

    float xx[2], M[2];
    bool  pos[2];
    #pragma unroll
    for (int k = 0; k < 2; k++) {
        int jj = 1 + ty + k * 8, ii = 1 + tx;
        float m;
        MAX9(xs, jj - 1, ii - 1, m);
        M[k]  = m;
        xx[k] = xs[jj][ii];
        pos[k] = __fsub_rn(__fmul_rn(m, gd[k]), xx[k]) > 0.05f;
        unsigned rowmask = __ballot_sync(0xffffffffu, pos[k]);
        if (tx == 0) s_rowpos[ty + k * 8] = rowmask;
    }
    int any = __syncthreads_or((pos[0] || pos[1]) ? 1 : 0);

    if (!any) {
        if (selfchg) {
            #pragma unroll
            for (int k = 0; k < 2; k++)
                xout[(r0 + ty + k * 8) * WW + c0 + tx] = xx[k];
        }
        if (tid == 0 && ((posw >> bx) & 1ull))
            atomicAnd(&g_posmask[by], ~(1ull << bx));
        return;
    }

    #pragma unroll
    for (int k = 0; k < 3; k++) {
        int s = tid + k * 256;
        bool sv = s < NSLOT;
        int ss = sv ? s : 0;
        int j = ss / SW, ii = ss % SW;
        float x = sv ? xs[j][ii] : 0.0f;
        unsigned rm = 0;
        #pragma unroll
        for (int dr = 0; dr < 3; dr++) {
            int cr = j - 2 + dr;
            if (cr >= 0 && cr < TH) rm |= s_rowpos[cr];
        }
        ull rm2 = ((ull)rm) << 2;
        bool needc = (((rm2 >> ii) & 7ull) != 0ull) && (x > 0.05f);
        float y1 = 0.0f;
        if (__ballot_sync(0xffffffffu, needc)) {
            uint32_t p = (uint32_t)((r0 - 1 + j) * WW + (c0 - 1 + ii));
            float u = bits_to_uniform(pbits(k1a, k1b, p));
            float f = __fadd_rn(0.9999f, __fmul_rn(1e-4f, u));
            y1 = __fmul_rn(x, f);
        }
        if (sv) ys[j][ii] = y1;
    }
    __syncthreads();

    int chg = 0;
    #pragma unroll
    for (int k = 0; k < 2; k++) {
        int jj = 1 + ty + k * 8, ii = 1 + tx;
        float m;
        MAX9(ys, jj - 1, ii - 1, m);
        uint32_t p = (uint32_t)((r0 + ty + k * 8) * WW + c0 + tx);
        float y4 = 0.0f;
        if (__ballot_sync(0xffffffffu, pos[k])) {
            uint32_t bits = pbits(k2a, k2b, p);
            bool coin = ((bits >> 9) > 0x400000u);   // u > 0.5 strictly
            if (coin && m > 0.0f) y4 = __fmul_rn(m, gd[k]);
        }
        float d  = __fsub_rn(y4, xx[k]);
        float y5 = (d > 0.05f) ? y4 : 0.0f;
        float out = fmaxf(y5, xx[k]);
        xout[p] = out;
        chg |= (out != xx[k]) ? 1 : 0;
    }
    int anychg = __syncthreads_or(chg);
    if (tid == 0) {
        ull bit = 1ull << bx;
        if (anychg) atomicOr(&g_chmask[cur][by], bit);
        if (!((posw >> bx) & 1ull)) atomicOr(&g_posmask[by], bit);
    }
}

// ---------------------------------------------------------------------------
// TWO fused iterations per launch, 4 tiles/block (2048 blocks). Iter A on
// core+1 (ring recomputed bit-identically from the same per-pixel keys),
// iter B on core. Sound wake: dilate1(changed) | dilate1(pos).
// ---------------------------------------------------------------------------
__global__ __launch_bounds__(256)
void fused_kernel(const float* __restrict__ xin, float* __restrict__ xout,
                  const float* __restrict__ good,
                  uint32_t kA1a, uint32_t kA1b, uint32_t kA2a, uint32_t kA2b,
                  uint32_t kB1a, uint32_t kB1b, uint32_t kB2a, uint32_t kB2b,
                  int prev, int cur, int nxt) {
    __shared__ float xs[SH2][SW2];
    __shared__ float ys[SH2][SW2];
    __shared__ float xa[SHA][SWA];
    __shared__ float gs[SHA][SWA];
    __shared__ ull s_posA[SHA];
    __shared__ unsigned s_rowposB[TH];

    const int tid = threadIdx.x;
    const int tx = tid & 31;
    const int ty = tid >> 5;

    if (blockIdx.x < NBY && tid == 0) g_chmask[nxt][blockIdx.x] = 0ull;

    const int tbase = blockIdx.x * 4;
    const int by  = tbase >> 6;
    const int bx0 = tbase & 63;

    // wake: dilate1(changed | pos) over the 3 tile rows
    ull needw = 0ull;
    const ull chm = g_chmask[prev][by];
    {
        ull a = chm | g_posmask[by];
        needw |= a | (a << 1) | (a >> 1);
        if (by > 0) {
            ull b = g_chmask[prev][by - 1] | g_posmask[by - 1];
            needw |= b | (b << 1) | (b >> 1);
        }
        if (by < NBY - 1) {
            ull c = g_chmask[prev][by + 1] | g_posmask[by + 1];
            needw |= c | (c << 1) | (c >> 1);
        }
    }
    const ull posw = g_posmask[by];

    #pragma unroll
    for (int kt = 0; kt < 4; kt++) {
        const int bx = bx0 + kt;
        if (!((needw >> bx) & 1ull)) continue;   // uniform across block

        const int selfchg = (int)((chm >> bx) & 1ull);
        const int c0 = bx * TW, r0 = by * TH;

        __syncthreads();                         // smem reuse barrier

        #pragma unroll
        for (int q = 0; q < 3; q++) {
            int s = tid + q * 256;
            if (s < NSLOT2) {
                int j = s / SW2, i = s % SW2;
                int r = r0 - 2 + j, c = c0 - 2 + i;
                bool ok = (r >= 0) && (r < HH) && (c >= 0) && (c < WW);
                xs[j][i] = ok ? xin[r * WW + c] : 0.0f;
            }
        }
        if (tid < SHA) s_posA[tid] = 0ull;
        __syncthreads();

        bool posAv[3]; float xxA[3], gsv[3];
        #pragma unroll
        for (int q = 0; q < 3; q++) {
            int s = tid + q * 256;
            bool sv = s < NSLOTA;
            posAv[q] = false; xxA[q] = 0.0f; gsv[q] = 0.0f;
            if (sv) {
                int a = s / SWA, b = s % SWA;
                int r = r0 - 1 + a, c = c0 - 1 + b;
                bool inim = (r >= 0) && (r < HH) && (c >= 0) && (c < WW);
                float g = inim ? good[r * WW + c] : 0.0f;
                gsv[q] = g; gs[a][b] = g;
                float x = xs[a + 1][b + 1];
                xxA[q] = x;
                float M; MAX9(xs, a, b, M);
                if (inim && (__fsub_rn(__fmul_rn(M, g), x) > 0.05f)) {
                    posAv[q] = true;
                    atomicOr(&s_posA[a], 1ull << b);
                }
            }
        }
        int anyA = __syncthreads_or((posAv[0] || posAv[1] || posAv[2]) ? 1 : 0);

        if (!anyA) {
            if (selfchg) {
                #pragma unroll
                for (int k = 0; k < 2; k++) {
                    int rr = ty + k * 8, cc = tx;
                    xout[(r0 + rr) * WW + (c0 + cc)] = xs[rr + 2][cc + 2];
                }
            }
            if (tid == 0 && ((posw >> bx) & 1ull))
                atomicAnd(&g_posmask[by], ~(1ull << bx));
            continue;
        }

        // iter A noise over halo2 region (gated: posA dilated 1, x > 0.05)
        #pragma unroll
        for (int q = 0; q < 3; q++) {
            int s = tid + q * 256;
            bool sv = s < NSLOT2;
            int j = sv ? s / SW2 : 0, i = sv ? s % SW2 : 0;
            float x = sv ? xs[j][i] : 0.0f;
            ull rm = 0ull;
            #pragma unroll
            for (int dr = 0; dr < 3; dr++) {
                int ar = j - 2 + dr;
                if (ar >= 0 && ar < SHA) rm |= s_posA[ar];
            }
            ull rm2 = rm << 2;
            bool needc = (((rm2 >> i) & 7ull) != 0ull) && (x > 0.05f);
            float y1 = 0.0f;
            if (__ballot_sync(0xffffffffu, needc)) {
                uint32_t p = (uint32_t)((r0 - 2 + j) * WW + (c0 - 2 + i));
                float u = bits_to_uniform(pbits(kA1a, kA1b, p));
                float f = __fadd_rn(0.9999f, __fmul_rn(1e-4f, u));
                y1 = __fmul_rn(x, f);
            }
            if (sv) ys[j][i] = y1;
        }
        __syncthreads();

        // iter A update over core+1 -> xa
        #pragma unroll
        for (int q = 0; q < 3; q++) {
            int s = tid + q * 256;
            bool sv = s < NSLOTA;
            int a = sv ? s / SWA : 0, b = sv ? s % SWA : 0;
            float m; MAX9(ys, a, b, m);
            float y4 = 0.0f;
            if (__ballot_sync(0xffffffffu, posAv[q])) {
                uint32_t p = (uint32_t)((r0 - 1 + a) * WW + (c0 - 1 + b));
                uint32_t bits = pbits(kA2a, kA2b, p);
                bool coin = ((bits >> 9) > 0x400000u);
                if (coin && m > 0.0f) y4 = __fmul_rn(m, gsv[q]);
            }
            float d  = __fsub_rn(y4, xxA[q]);
            float y5 = (d > 0.05f) ? y4 : 0.0f;
            if (sv) xa[a][b] = fmaxf(y5, xxA[q]);
        }
        __syncthreads();

        // iter B pos pass over core
        bool posB[2]; float xab[2], gdB[2];
        #pragma unroll
        for (int k = 0; k < 2; k++) {
            int rr = ty + k * 8, cc = tx;
            float M; MAX9(xa, rr, cc, M);
            xab[k] = xa[rr + 1][cc + 1];
            gdB[k] = gs[rr + 1][cc + 1];
            posB[k] = __fsub_rn(__fmul_rn(M, gdB[k]), xab[k]) > 0.05f;
            unsigned rowmask = __ballot_sync(0xffffffffu, posB[k]);
            if (tx == 0) s_rowposB[rr] = rowmask;
        }
        int anyB = __syncthreads_or((posB[0] || posB[1]) ? 1 : 0);

        if (!anyB) {
            int chg = 0;
            #pragma unroll
            for (int k = 0; k < 2; k++) {
                int rr = ty + k * 8, cc = tx;
                float out = xab[k];
                xout[(r0 + rr) * WW + (c0 + cc)] = out;
                chg |= (out != xs[rr + 2][cc + 2]) ? 1 : 0;
            }
            int anychg = __syncthreads_or(chg);
            if (tid == 0) {
                if (anychg) atomicOr(&g_chmask[cur][by], 1ull << bx);
                if ((posw >> bx) & 1ull)
                    atomicAnd(&g_posmask[by], ~(1ull << bx));
            }
            continue;
        }

        // iter B noise over core+1 (reads xa)
        #pragma unroll
        for (int q = 0; q < 3; q++) {
            int s = tid + q * 256;
            bool sv = s < NSLOTA;
            int a = sv ? s / SWA : 0, b = sv ? s % SWA : 0;
            float x = sv ? xa[a][b] : 0.0f;
            unsigned rm = 0;
            #pragma unroll
            for (int dr = 0; dr < 3; dr++) {
                int br = a - 2 + dr;
                if (br >= 0 && br < TH) rm |= s_rowposB[br];
            }
            ull rm2 = ((ull)rm) << 2;
            bool needc = (((rm2 >> b) & 7ull) != 0ull) && (x > 0.05f);
            float y1 = 0.0f;
            if (__ballot_sync(0xffffffffu, needc)) {
                uint32_t p = (uint32_t)((r0 - 1 + a) * WW + (c0 - 1 + b));
                float u = bits_to_uniform(pbits(kB1a, kB1b, p));
                float f = __fadd_rn(0.9999f, __fmul_rn(1e-4f, u));
                y1 = __fmul_rn(x, f);
            }
            if (sv) ys[a][b] = y1;
        }
        __syncthreads();

        // iter B final over core + write
        int chg = 0;
        #pragma unroll
        for (int k = 0; k < 2; k++) {
            int rr = ty + k * 8, cc = tx;
            float m; MAX9(ys, rr, cc, m);
            uint32_t p = (uint32_t)((r0 + rr) * WW + (c0 + cc));
            float y4 = 0.0f;
            if (__ballot_sync(0xffffffffu, posB[k])) {
                uint32_t bits = pbits(kB2a, kB2b, p);
                bool coin = ((bits >> 9) > 0x400000u);
                if (coin && m > 0.0f) y4 = __fmul_rn(m, gdB[k]);
            }
            float d  = __fsub_rn(y4, xab[k]);
            float y5 = (d > 0.05f) ? y4 : 0.0f;
            float out = fmaxf(y5, xab[k]);
            xout[p] = out;
            chg |= (out != xs[rr + 2][cc + 2]) ? 1 : 0;
        }
        int anychg = __syncthreads_or(chg);
        if (tid == 0) {
            ull bit = 1ull << bx;
            if (anychg) atomicOr(&g_chmask[cur][by], bit);
            if (!((posw >> bx) & 1ull)) atomicOr(&g_posmask[by], bit);
        }
    }
}

// ---------------------------------------------------------------------------
// Host: init -> scratch; 26 growth + 37 fused = 63 launches covering 100
// iterations; odd swap count lands the final state in d_out.
// ---------------------------------------------------------------------------
static void iter_keys(int i, uint32_t* k) {
    uint32_t f0, f1;
    tf2x32(0u, 42u, 0u, (uint32_t)i, f0, f1);        // fold_in
    tf2x32(f0, f1, 0u, 0u, k[0], k[1]);              // split k1
    tf2x32(f0, f1, 0u, 1u, k[2], k[3]);              // split k2
}

extern "C" void kernel_launch(void* const* d_in, const int* in_sizes, int n_in,
                              void* d_out, int out_size) {
    const float* seed = (const float*)d_in[0];
    const float* hab  = (const float*)d_in[1];
    const float* good = (const float*)d_in[2];
    float* xout = (float*)d_out;

    float* scratch = nullptr;
    cudaGetSymbolAddress((void**)&scratch, g_scratch);

    init_kernel<<<(NPIX / 4 + 255) / 256, 256>>>(seed, hab, good, scratch);

    const float* cura = scratch;
    float*       alt  = xout;
    int l = 0;

    for (int i = 0; i < GROWTH_ITERS; i++, l++) {
        uint32_t k[4];
        iter_keys(i, k);
        growth_kernel<<<NB, 256>>>(cura, alt, good, k[0], k[1], k[2], k[3],
                                   (l + 2) % 3, l % 3, (l + 1) % 3);
        const float* t = cura; cura = alt; alt = (float*)t;
    }

    for (int t = 0; t < FUSED_LAUNCHES; t++, l++) {
        uint32_t kA[4], kB[4];
        iter_keys(GROWTH_ITERS + 2 * t, kA);
        iter_keys(GROWTH_ITERS + 2 * t + 1, kB);
        fused_kernel<<<NB / 4, 256>>>(cura, alt, good,
                                      kA[0], kA[1], kA[2], kA[3],
                                      kB[0], kB[1], kB[2], kB[3],
                                      (l + 2) % 3, l % 3, (l + 1) % 3);
        const float* tt = cura; cura = alt; alt = (float*)tt;
    }
    // 63 launches (odd): started in scratch -> final state lands in d_out
}